// round 13
// baseline (speedup 1.0000x reference)
#include <cuda_runtime.h>

#define T_STEPS 20

// FSET: float 1.0f/0.0f result of (a > b) in ONE alu instruction.
__device__ __forceinline__ float fset_gt(float a, float b) {
    float d; asm("set.gt.f32.f32 %0, %1, %2;" : "=f"(d) : "f"(a), "f"(b)); return d;
}

__global__ void __launch_bounds__(256) xornet_snn_kernel(
    const float4* __restrict__ x4,   // x [B,2] as float4 pairs
    const float*  __restrict__ w1,   // [4,2]
    const float*  __restrict__ w2,   // [1,4]
    float*        __restrict__ out,  // [T, B]
    int B)
{
    const int i  = blockIdx.x * blockDim.x + threadIdx.x;  // group of 4 batch elems
    const int b0 = i * 4;
    if (b0 >= B) return;

    const float4 xa = x4[2 * i + 0];  // b0:{x0,x1}, b1:{x0,x1}
    const float4 xb = x4[2 * i + 1];  // b2:{x0,x1}, b3:{x0,x1}
    const float px0[4] = {xa.x, xa.z, xb.x, xb.z};
    const float px1[4] = {xa.y, xa.w, xb.y, xb.w};

    float w1v[4][2];
#pragma unroll
    for (int h = 0; h < 4; h++) {
        w1v[h][0] = __ldg(&w1[2 * h + 0]);
        w1v[h][1] = __ldg(&w1[2 * h + 1]);
    }
    float w2v[4];
#pragma unroll
    for (int h = 0; h < 4; h++) w2v[h] = __ldg(&w2[h]);

    // cur[l][h]: same fma chain as all passing rounds (bit-identical).
    float cur[4][4];
#pragma unroll
    for (int l = 0; l < 4; l++)
#pragma unroll
        for (int h = 0; h < 4; h++)
            cur[l][h] = fmaf(px1[l], w1v[h][1], px0[l] * w1v[h][0]);

    // Scalar state. All constant-multiplier fmas are written with a LITERAL
    // multiplicand so ptxas can emit the FFMA-imm encoding (rt=1/SMSP, 2x the
    // throughput of 3-reg FFMA and 4x packed f32x2 per lane).
    float m1[4][4], s1[4][4];
#pragma unroll
    for (int l = 0; l < 4; l++)
#pragma unroll
        for (int h = 0; h < 4; h++) { m1[l][h] = 0.0f; s1[l][h] = 0.0f; }
    float m2[4] = {0.f, 0.f, 0.f, 0.f};
    float s2[4] = {0.f, 0.f, 0.f, 0.f};

    float* outp = out + b0;

#pragma unroll 4
    for (int t = 0; t < T_STEPS; t++) {
#pragma unroll
        for (int l = 0; l < 4; l++) {
#pragma unroll
            for (int h = 0; h < 4; h++) {
                // m = m*0.9 + cur            (FFMA-imm, rt=1)
                float m = fmaf(m1[l][h], 0.9f, cur[l][h]);
                // m = s*(-1) + m == m - s    (FFMA-imm, rt=1; bit-identical to FADD/fsub2)
                m = fmaf(s1[l][h], -1.0f, m);
                m1[l][h] = m;
                s1[l][h] = fset_gt(m, 1.0f);          // 1 alu op
            }
            // o = spk1 . w2 : s*w products are EXACT (s in {0,1}) -> chain
            // rounding identical to every previous passing round.
            float o = s1[l][0] * w2v[0];
            o = fmaf(s1[l][1], w2v[1], o);
            o = fmaf(s1[l][2], w2v[2], o);
            o = fmaf(s1[l][3], w2v[3], o);

            float m = fmaf(m2[l], 0.9f, o);           // FFMA-imm
            m = fmaf(s2[l], -1.0f, m);                // FFMA-imm
            m2[l] = m;
            s2[l] = fset_gt(m, 1.0f);
        }
        *reinterpret_cast<float4*>(outp) =
            make_float4(s2[0], s2[1], s2[2], s2[3]);
        outp += B;  // next timestep plane
    }
}

extern "C" void kernel_launch(void* const* d_in, const int* in_sizes, int n_in,
                              void* d_out, int out_size)
{
    const float* x  = (const float*)d_in[0];   // [B, 2]
    const float* w1 = (const float*)d_in[1];   // [4, 2]
    const float* w2 = (const float*)d_in[2];   // [1, 4]
    float* out      = (float*)d_out;           // [T, B, 1]

    const int B = in_sizes[0] / 2;
    const int nthreads = B / 4;                // 4 batch elems per thread
    const int block = 256;
    const int grid = (nthreads + block - 1) / block;

    xornet_snn_kernel<<<grid, block>>>((const float4*)x, w1, w2, out, B);
}

// round 14
// speedup vs baseline: 1.2748x; 1.2748x over previous
#include <cuda_runtime.h>

#define T_STEPS 20

typedef unsigned long long u64;

// Compiler-visible pack/unpack: register-pair aliasing, no forced MOVs.
union f2u {
    u64 v;
    float2 f;
};
__device__ __forceinline__ u64 pack2(float x, float y) {
    f2u t; t.f.x = x; t.f.y = y; return t.v;
}
__device__ __forceinline__ void unpack2(u64 v, float& x, float& y) {
    f2u t; t.v = v; x = t.f.x; y = t.f.y;
}
// Packed fma: each half independent fma.rn.f32 -> bit-identical to scalar FFMA.
__device__ __forceinline__ u64 ffma2(u64 a, u64 b, u64 c) {
    u64 d; asm("fma.rn.f32x2 %0, %1, %2, %3;" : "=l"(d) : "l"(a), "l"(b), "l"(c)); return d;
}
// Packed subtract: round(a-b) == fma(b,-1,a) value-for-value.
__device__ __forceinline__ u64 fsub2(u64 a, u64 b) {
    u64 d; asm("sub.rn.f32x2 %0, %1, %2;" : "=l"(d) : "l"(a), "l"(b)); return d;
}
// FSET: float 1.0f/0.0f result of (a > b) in ONE instruction.
__device__ __forceinline__ float fset_gt(float a, float b) {
    float d; asm("set.gt.f32.f32 %0, %1, %2;" : "=f"(d) : "f"(a), "f"(b)); return d;
}

// 4-bit LUT index from 4 spike floats (0.0f / 1.0f).
// 1.0f = 0x3F800000: high byte 0x3F (bit0 set), 0.0f high byte 0x00.
// Gather the 4 high bytes, mask bit0 of each, magic-multiply to pack
// b0..b3 into bits 24..27, then shift/mask to a byte offset (idx*128).
__device__ __forceinline__ unsigned lut_off(float s0, float s1, float s2, float s3) {
    unsigned a01 = __byte_perm(__float_as_uint(s0), __float_as_uint(s1), 0x0073);
    unsigned a23 = __byte_perm(__float_as_uint(s2), __float_as_uint(s3), 0x7300);
    unsigned bits = (a01 | a23) & 0x01010101u;       // one LOP3
    return ((bits * 0x01020408u) >> 17) & 0x780u;    // idx*128 (bytes)
}

__global__ void __launch_bounds__(256) xornet_snn_kernel(
    const float4* __restrict__ x4,   // x [B,2] as float4 pairs
    const float*  __restrict__ w1,   // [4,2]
    const float*  __restrict__ w2,   // [1,4]
    float*        __restrict__ out,  // [T, B]
    int B)
{
    // LUT of all 16 possible spk1.w2 dot values, replicated per lane
    // (addr = idx*128 + lane*4 -> bank == lane -> conflict-free).
    __shared__ float lut[16 * 32];

    const int tid  = threadIdx.x;
    const int lane = tid & 31;

    float w2v[4];
#pragma unroll
    for (int h = 0; h < 4; h++) w2v[h] = __ldg(&w2[h]);

    // Build LUT with the EXACT dot chain used before: s0*w0; fma(s1,w1,.);
    // fma(s2,w2,.); fma(s3,w3,.) with s in {0,1} -> bit-identical values.
    {
        const int e0 = tid >> 5;                 // 0..7, each handles e0 and e0+8
#pragma unroll
        for (int k = 0; k < 2; k++) {
            const int e = e0 + 8 * k;
            float s0 = (e & 1) ? 1.0f : 0.0f;
            float s1 = (e & 2) ? 1.0f : 0.0f;
            float s2 = (e & 4) ? 1.0f : 0.0f;
            float s3 = (e & 8) ? 1.0f : 0.0f;
            float o = s0 * w2v[0];
            o = fmaf(s1, w2v[1], o);
            o = fmaf(s2, w2v[2], o);
            o = fmaf(s3, w2v[3], o);
            lut[e * 32 + lane] = o;
        }
    }
    __syncthreads();

    const int i  = blockIdx.x * blockDim.x + tid;   // group of 4 batch elems
    const int b0 = i * 4;
    if (b0 >= B) return;

    const char* lbase = (const char*)lut + (lane << 2);

    const float4 xa = x4[2 * i + 0];  // b0:{x0,x1}, b1:{x0,x1}
    const float4 xb = x4[2 * i + 1];  // b2:{x0,x1}, b3:{x0,x1}
    const float px0[4] = {xa.x, xa.z, xb.x, xb.z};
    const float px1[4] = {xa.y, xa.w, xb.y, xb.w};

    float w1v[4][2];
#pragma unroll
    for (int h = 0; h < 4; h++) {
        w1v[h][0] = __ldg(&w1[2 * h + 0]);
        w1v[h][1] = __ldg(&w1[2 * h + 1]);
    }

    // cur[p][h]: packed pair of lanes (2p,2p+1); same fma chain (bit-identical).
    u64 cur[2][4];
#pragma unroll
    for (int p = 0; p < 2; p++)
#pragma unroll
        for (int h = 0; h < 4; h++) {
            float c0 = fmaf(px1[2 * p + 0], w1v[h][1], px0[2 * p + 0] * w1v[h][0]);
            float c1 = fmaf(px1[2 * p + 1], w1v[h][1], px0[2 * p + 1] * w1v[h][0]);
            cur[p][h] = pack2(c0, c1);
        }

    const u64 BETA2 = pack2(0.9f, 0.9f);
    const u64 ZERO2 = pack2(0.0f, 0.0f);

    // Packed membranes + previous spikes (prev spike == this step's reset;
    // (m-1>0) <=> (m>1) exactly in fp32).
    u64 m1[2][4], s1[2][4], m2[2], s2[2];
#pragma unroll
    for (int p = 0; p < 2; p++) {
#pragma unroll
        for (int h = 0; h < 4; h++) { m1[p][h] = ZERO2; s1[p][h] = ZERO2; }
        m2[p] = ZERO2; s2[p] = ZERO2;
    }

    float* outp = out + b0;

#pragma unroll 4
    for (int t = 0; t < T_STEPS; t++) {
        float so[2][2];
#pragma unroll
        for (int p = 0; p < 2; p++) {
            float sl[4], sh[4];   // spike floats for the two lanes of this pair
#pragma unroll
            for (int h = 0; h < 4; h++) {
                u64 m = ffma2(BETA2, m1[p][h], cur[p][h]);   // beta*m + cur
                m = fsub2(m, s1[p][h]);                      // - prev spike (exact)
                m1[p][h] = m;
                float lo, hi; unpack2(m, lo, hi);
                sl[h] = fset_gt(lo, 1.0f);
                sh[h] = fset_gt(hi, 1.0f);
                s1[p][h] = pack2(sl[h], sh[h]);
            }
            // Dot via LUT: bit-identical to the fmul/fma chain (entries built
            // with the same op sequence). ALU index math + conflict-free LDS.
            float olo = *(const float*)(lbase + lut_off(sl[0], sl[1], sl[2], sl[3]));
            float ohi = *(const float*)(lbase + lut_off(sh[0], sh[1], sh[2], sh[3]));
            u64 o = pack2(olo, ohi);

            u64 m = ffma2(BETA2, m2[p], o);
            m = fsub2(m, s2[p]);
            m2[p] = m;
            float lo, hi; unpack2(m, lo, hi);
            so[p][0] = fset_gt(lo, 1.0f);
            so[p][1] = fset_gt(hi, 1.0f);
            s2[p] = pack2(so[p][0], so[p][1]);
        }
        *reinterpret_cast<float4*>(outp) =
            make_float4(so[0][0], so[0][1], so[1][0], so[1][1]);
        outp += B;  // next timestep plane
    }
}

extern "C" void kernel_launch(void* const* d_in, const int* in_sizes, int n_in,
                              void* d_out, int out_size)
{
    const float* x  = (const float*)d_in[0];   // [B, 2]
    const float* w1 = (const float*)d_in[1];   // [4, 2]
    const float* w2 = (const float*)d_in[2];   // [1, 4]
    float* out      = (float*)d_out;           // [T, B, 1]

    const int B = in_sizes[0] / 2;
    const int nthreads = B / 4;                // 4 batch elems per thread
    const int block = 256;
    const int grid = (nthreads + block - 1) / block;

    xornet_snn_kernel<<<grid, block>>>((const float4*)x, w1, w2, out, B);
}

// round 15
// speedup vs baseline: 1.7078x; 1.3397x over previous
#include <cuda_runtime.h>

#define T_STEPS 20

typedef unsigned long long u64;

union f2u {
    u64 v;
    float2 f;
};
__device__ __forceinline__ u64 pack2(float x, float y) {
    f2u t; t.f.x = x; t.f.y = y; return t.v;
}
__device__ __forceinline__ void unpack2(u64 v, float& x, float& y) {
    f2u t; t.v = v; x = t.f.x; y = t.f.y;
}
// Packed fma: each half independent fma.rn.f32 -> bit-identical to scalar FFMA.
__device__ __forceinline__ u64 ffma2(u64 a, u64 b, u64 c) {
    u64 d; asm("fma.rn.f32x2 %0, %1, %2, %3;" : "=l"(d) : "l"(a), "l"(b), "l"(c)); return d;
}
__device__ __forceinline__ u64 fmul2(u64 a, u64 b) {
    u64 d; asm("mul.rn.f32x2 %0, %1, %2;" : "=l"(d) : "l"(a), "l"(b)); return d;
}
// Packed subtract: round(a-b) == fma(b,-1,a) value-for-value.
__device__ __forceinline__ u64 fsub2(u64 a, u64 b) {
    u64 d; asm("sub.rn.f32x2 %0, %1, %2;" : "=l"(d) : "l"(a), "l"(b)); return d;
}
// Fused spike pair: both halves of the packed membrane compared against 1.0f,
// result re-formed as a packed float pair (1.0/0.0 halves). The mov.b64
// split/join inside ONE asm block lets ptxas allocate lo/hi/a/b onto the pair
// registers directly and elide the moves (sources die immediately) -> ideally
// just 2 FSET instructions, no pack/unpack MOVs.
__device__ __forceinline__ u64 fset_gt1_pair(u64 m) {
    u64 s;
    asm("{\n\t"
        ".reg .f32 lo, hi, a, b;\n\t"
        "mov.b64 {lo, hi}, %1;\n\t"
        "set.gt.f32.f32 a, lo, 0f3F800000;\n\t"   // a = (m_lo > 1.0f) ? 1.0f : 0.0f
        "set.gt.f32.f32 b, hi, 0f3F800000;\n\t"
        "mov.b64 %0, {a, b};\n\t"
        "}" : "=l"(s) : "l"(m));
    return s;
}

__global__ void __launch_bounds__(256) xornet_snn_kernel(
    const float4* __restrict__ x4,   // x [B,2] as float4 pairs
    const float*  __restrict__ w1,   // [4,2]
    const float*  __restrict__ w2,   // [1,4]
    float*        __restrict__ out,  // [T, B]
    int B)
{
    const int i  = blockIdx.x * blockDim.x + threadIdx.x;  // group of 4 batch elems
    const int b0 = i * 4;
    if (b0 >= B) return;

    const float4 xa = x4[2 * i + 0];  // b0:{x0,x1}, b1:{x0,x1}
    const float4 xb = x4[2 * i + 1];  // b2:{x0,x1}, b3:{x0,x1}
    const float px0[4] = {xa.x, xa.z, xb.x, xb.z};
    const float px1[4] = {xa.y, xa.w, xb.y, xb.w};

    float w1v[4][2];
#pragma unroll
    for (int h = 0; h < 4; h++) {
        w1v[h][0] = __ldg(&w1[2 * h + 0]);
        w1v[h][1] = __ldg(&w1[2 * h + 1]);
    }
    u64 W2[4];
#pragma unroll
    for (int h = 0; h < 4; h++) {
        float w = __ldg(&w2[h]);
        W2[h] = pack2(w, w);
    }

    // cur[p][h]: packed pair of lanes (2p,2p+1); same fma chain (bit-identical).
    u64 cur[2][4];
#pragma unroll
    for (int p = 0; p < 2; p++)
#pragma unroll
        for (int h = 0; h < 4; h++) {
            float c0 = fmaf(px1[2 * p + 0], w1v[h][1], px0[2 * p + 0] * w1v[h][0]);
            float c1 = fmaf(px1[2 * p + 1], w1v[h][1], px0[2 * p + 1] * w1v[h][0]);
            cur[p][h] = pack2(c0, c1);
        }

    const u64 BETA2 = pack2(0.9f, 0.9f);
    const u64 ZERO2 = pack2(0.0f, 0.0f);

    // Packed membranes + previous spikes (prev spike == this step's reset;
    // (m-1>0) <=> (m>1) exactly in fp32).
    u64 m1[2][4], s1[2][4], m2[2], s2[2];
#pragma unroll
    for (int p = 0; p < 2; p++) {
#pragma unroll
        for (int h = 0; h < 4; h++) { m1[p][h] = ZERO2; s1[p][h] = ZERO2; }
        m2[p] = ZERO2; s2[p] = ZERO2;
    }

    float* outp = out + b0;

#pragma unroll
    for (int t = 0; t < T_STEPS; t++) {
#pragma unroll
        for (int p = 0; p < 2; p++) {
#pragma unroll
            for (int h = 0; h < 4; h++) {
                u64 m = ffma2(BETA2, m1[p][h], cur[p][h]);   // beta*m + cur
                m = fsub2(m, s1[p][h]);                      // - prev spike (exact)
                m1[p][h] = m;
                s1[p][h] = fset_gt1_pair(m);                 // 2x FSET, pair-direct
            }
            // o = spk1 . w2 : packed mul + fma chain, same order & values as scalar
            u64 o = fmul2(s1[p][0], W2[0]);
            o = ffma2(s1[p][1], W2[1], o);
            o = ffma2(s1[p][2], W2[2], o);
            o = ffma2(s1[p][3], W2[3], o);

            u64 m = ffma2(BETA2, m2[p], o);
            m = fsub2(m, s2[p]);
            m2[p] = m;
            s2[p] = fset_gt1_pair(m);
        }
        float a, b, c, d;
        unpack2(s2[0], a, b);
        unpack2(s2[1], c, d);
        *reinterpret_cast<float4*>(outp) = make_float4(a, b, c, d);
        outp += B;  // next timestep plane
    }
}

extern "C" void kernel_launch(void* const* d_in, const int* in_sizes, int n_in,
                              void* d_out, int out_size)
{
    const float* x  = (const float*)d_in[0];   // [B, 2]
    const float* w1 = (const float*)d_in[1];   // [4, 2]
    const float* w2 = (const float*)d_in[2];   // [1, 4]
    float* out      = (float*)d_out;           // [T, B, 1]

    const int B = in_sizes[0] / 2;
    const int nthreads = B / 4;                // 4 batch elems per thread
    const int block = 256;
    const int grid = (nthreads + block - 1) / block;

    xornet_snn_kernel<<<grid, block>>>((const float4*)x, w1, w2, out, B);
}